// round 14
// baseline (speedup 1.0000x reference)
#include <cuda_runtime.h>
#include <cuda_fp16.h>
#include <cstdint>

// ============================================================
// AWQLinear via fp16 mma.sync m16n8k16 (same mantissa as tf32).
// y = (x/alpha) @ W_hat^T + bias, M=4096 N=11008 K=4096.
// R13 = R11 (256x128 tiles, 4 stages, s0-prefetch, tail split)
// with ONE sync point per 2 k-chunks: copy kt+2 & kt+3 at block
// entry, process kt & kt+1, wait_group 0 + barrier.
// ============================================================

#define IN_F   4096
#define OUT_F  11008
#define MROWS  4096
#define NKT    64
#define A_BLK_B32 8192
#define B_BLK_B32 4096
#define STAGE_BYTES ((A_BLK_B32 + B_BLK_B32) * 4)     // 48KB
#define SMEM_BYTES (4 * STAGE_BYTES)                  // 192KB
#define A_KT_BYTES (A_BLK_B32 * 4)
#define B_KT_BYTES (B_BLK_B32 * 4)

#define NTILES     1376          // 16 x 86
#define FULL_TILES 1332          // 9 waves x 148
#define SPLIT_TILES (NTILES - FULL_TILES)             // 44
#define GRID_CTAS  (FULL_TILES + 2 * SPLIT_TILES)     // 1420

#define XCHUNKS (MROWS * IN_F / 8)
#define WCHUNKS (OUT_F * IN_F / 8)
#define WBLOCKS (WCHUNKS / 256)                 // 22016
#define XBLOCKS (XCHUNKS / 256)                 // 8192

__device__ __half2 g_A[(size_t)XCHUNKS * 4];    // 32MB
__device__ __half2 g_B[(size_t)WCHUNKS * 4];    // 90MB

// ---------------- helpers ----------------
__device__ __forceinline__ uint32_t smem_u32(const void* p) {
    uint32_t a;
    asm("{ .reg .u64 t; cvta.to.shared.u64 t, %1; cvt.u32.u64 %0, t; }"
        : "=r"(a) : "l"(p));
    return a;
}
__device__ __forceinline__ void cp16(uint32_t dst, const void* src) {
    asm volatile("cp.async.cg.shared.global [%0], [%1], 16;"
                 :: "r"(dst), "l"(src) : "memory");
}
#define CP_COMMIT() asm volatile("cp.async.commit_group;" ::: "memory")
#define CP_WAIT0()  asm volatile("cp.async.wait_group 0;" ::: "memory")

__device__ __forceinline__ void mma_f16(float4& d, const uint4 a,
                                        const uint32_t b0, const uint32_t b1) {
    asm("mma.sync.aligned.m16n8k16.row.col.f32.f16.f16.f32 "
        "{%0,%1,%2,%3}, {%4,%5,%6,%7}, {%8,%9}, {%0,%1,%2,%3};"
        : "+f"(d.x), "+f"(d.y), "+f"(d.z), "+f"(d.w)
        : "r"(a.x), "r"(a.y), "r"(a.z), "r"(a.w), "r"(b0), "r"(b1));
}
__device__ __forceinline__ uint32_t h2u(__half2 h) { return *(uint32_t*)&h; }

// ---------------- merged prep: 1 thread = one 16B fragment chunk --------
__global__ void prep_all_kernel(const float* __restrict__ x,
                                const float* __restrict__ alpha,
                                const int* __restrict__ q,
                                const float* __restrict__ sc) {
    int bid = blockIdx.x;
    if (bid < WBLOCKS) {
        int j = bid * 256 + threadIdx.x;
        int blk = j >> 10, c = j & 1023;
        int th = c & 31, jp = (c >> 5) & 7, s = c >> 8;
        int nb = blk >> 6, kt = blk & 63;
        int o0 = (nb << 7) + (jp << 4) + (th >> 2);
        int k0 = (kt << 6) + (s << 4) + ((th & 3) << 1);
        int sblk = (kt << 1) + (s >> 1);
        const int* q0 = q + ((size_t)o0 << 12) + k0;
        const int* q8 = q0 + (8 << 12);
        float s0 = sc[(o0 << 7) + sblk];
        float s1 = sc[((o0 + 8) << 7) + sblk];
        int2 a0 = *(const int2*)(q0);
        int2 a2 = *(const int2*)(q0 + 8);
        int2 b0 = *(const int2*)(q8);
        int2 b2 = *(const int2*)(q8 + 8);
        uint4 o;
        o.x = h2u(__floats2half2_rn((float)(a0.x - 8) * s0, (float)(a0.y - 8) * s0));
        o.y = h2u(__floats2half2_rn((float)(a2.x - 8) * s0, (float)(a2.y - 8) * s0));
        o.z = h2u(__floats2half2_rn((float)(b0.x - 8) * s1, (float)(b0.y - 8) * s1));
        o.w = h2u(__floats2half2_rn((float)(b2.x - 8) * s1, (float)(b2.y - 8) * s1));
        *(uint4*)(g_B + (size_t)j * 4) = o;
    } else {
        int j = (bid - WBLOCKS) * 256 + threadIdx.x;
        int blk = j >> 11, c = j & 2047;
        int th = c & 31, it = (c >> 5) & 15, s = c >> 9;
        int mb = blk >> 6, kt = blk & 63;
        int row0 = (mb << 8) + (it << 4) + (th >> 2);
        int k0 = (kt << 6) + (s << 4) + ((th & 3) << 1);
        const float* x0 = x + ((size_t)row0 << 12) + k0;
        const float* x8 = x0 + (8 << 12);
        float ia0 = 1.0f / alpha[k0],     ia1 = 1.0f / alpha[k0 + 1];
        float ia8 = 1.0f / alpha[k0 + 8], ia9 = 1.0f / alpha[k0 + 9];
        float2 v00 = *(const float2*)(x0);
        float2 v10 = *(const float2*)(x8);
        float2 v08 = *(const float2*)(x0 + 8);
        float2 v18 = *(const float2*)(x8 + 8);
        uint4 o;
        o.x = h2u(__floats2half2_rn(v00.x * ia0, v00.y * ia1));
        o.y = h2u(__floats2half2_rn(v10.x * ia0, v10.y * ia1));
        o.z = h2u(__floats2half2_rn(v08.x * ia8, v08.y * ia9));
        o.w = h2u(__floats2half2_rn(v18.x * ia8, v18.y * ia9));
        *(uint4*)(g_A + (size_t)j * 4) = o;
    }
}

// ---------------- tile worker, NIL = A-itiles per warp (4 full / 2 half) ----
template<int NIL>
__device__ __forceinline__ void run_tile(int mt, int nt, int h, char* sm,
                                         uint32_t sbase,
                                         const float* __restrict__ bias,
                                         float* __restrict__ out) {
    int tid = threadIdx.x, wid = tid >> 5, t = tid & 31;
    int wm = wid & 3, wn = wid >> 2;
    const int itbase = (NIL == 4) ? (wm << 2) : (h * 8 + wm * 2);

    const char* gA = (const char*)g_A + (size_t)mt * (NKT * A_KT_BYTES);
    const char* gB = (const char*)g_B + (size_t)nt * (NKT * B_KT_BYTES);

    auto copy_stage = [&](int kt, uint32_t pbase) {
        const char* srcA = gA + (size_t)kt * A_KT_BYTES;
        if (NIL == 4) {
#pragma unroll
            for (int r = 0; r < 8; r++) {
                uint32_t off = (uint32_t)(tid * 16 + r * 4096);
                cp16(sbase + pbase + off, srcA + off);
            }
        } else {
#pragma unroll
            for (int r = 0; r < 4; r++) {         // half: itiles h*8..h*8+7
                int idx = r * 256 + tid;
                int s = idx >> 8, itl = h * 8 + ((idx >> 5) & 7), th = idx & 31;
                uint32_t off = (uint32_t)((((s << 4) + itl) << 9) + (th << 4));
                cp16(sbase + pbase + off, srcA + off);
            }
        }
        const char* srcB = gB + (size_t)kt * B_KT_BYTES;
#pragma unroll
        for (int r = 0; r < 4; r++) {
            uint32_t off = (uint32_t)(tid * 16 + r * 4096);
            cp16(sbase + pbase + A_KT_BYTES + off, srcB + off);
        }
    };

    float4 acc[NIL][8];
#pragma unroll
    for (int i = 0; i < NIL; i++)
#pragma unroll
        for (int jj = 0; jj < 8; jj++) acc[i][jj] = make_float4(0.f, 0.f, 0.f, 0.f);

    const int aoff = itbase * 512 + t * 16;
    const int boff = A_KT_BYTES + wn * 2048 + t * 16;

    uint4 fa[2][NIL], fb[2][4];
    auto load_frag = [&](int bi, const char* stage, int s) {
        const char* ab = stage + s * 8192 + aoff;
        const char* bb = stage + s * 4096 + boff;
#pragma unroll
        for (int il = 0; il < NIL; il++) fa[bi][il] = *(const uint4*)(ab + il * 512);
#pragma unroll
        for (int pl = 0; pl < 4; pl++) fb[bi][pl] = *(const uint4*)(bb + pl * 512);
    };
    auto do_mma = [&](int bi) {
#pragma unroll
        for (int il = 0; il < NIL; il++)
#pragma unroll
            for (int jj = 0; jj < 8; jj++) {
                const uint4& bp = fb[bi][jj >> 1];
                if (jj & 1) mma_f16(acc[il][jj], fa[bi][il], bp.z, bp.w);
                else        mma_f16(acc[il][jj], fa[bi][il], bp.x, bp.y);
            }
    };

    // prologue: stages 0,1 resident & visible; no pending groups
    copy_stage(0, 0); CP_COMMIT();
    copy_stage(1, STAGE_BYTES); CP_COMMIT();
    CP_WAIT0();
    __syncthreads();

    // 2-kt block: ONE wait+barrier per 2 chunks.
    // Entry invariant: slots p,p+1 hold kt,kt+1 (visible); no pending groups.
    auto block2 = [&](int kt, int p) {
        const char* st0 = sm + (size_t)p * STAGE_BYTES;
        const char* st1 = sm + (size_t)((p + 1) & 3) * STAGE_BYTES;
        if (kt + 2 < NKT) copy_stage(kt + 2, (uint32_t)(((p + 2) & 3) * STAGE_BYTES));
        CP_COMMIT();
        if (kt + 3 < NKT) copy_stage(kt + 3, (uint32_t)(((p + 3) & 3) * STAGE_BYTES));
        CP_COMMIT();
        load_frag(0, st0, 0);                      // post-bar bubble (1 per 2 kt)
#pragma unroll
        for (int s = 0; s < 4; s++) {              // chunk kt
            int cur = s & 1;
            if (s < 3) load_frag(cur ^ 1, st0, s + 1);
            else       load_frag(cur ^ 1, st1, 0); // kt+1 s0 (resident since entry)
            do_mma(cur);
        }
#pragma unroll
        for (int s = 0; s < 4; s++) {              // chunk kt+1
            int cur = s & 1;
            if (s < 3) load_frag(cur ^ 1, st1, s + 1);
            do_mma(cur);
        }
        CP_WAIT0();          // kt+2, kt+3 arrived (issued a full block ago)
        __syncthreads();     // publish cross-thread; protect slot reuse
    };

    for (int kt = 0; kt < NKT; kt += 4) {
        block2(kt + 0, 0);
        block2(kt + 2, 2);
    }

    int quad = t >> 2, tq = t & 3;
    int col_base = nt * 128 + wn * 64;
#pragma unroll
    for (int il = 0; il < NIL; il++) {
        int r0 = mt * 256 + (itbase + il) * 16 + quad;
        float* o0 = out + (size_t)r0 * OUT_F;
        float* o1 = o0 + (size_t)8 * OUT_F;
#pragma unroll
        for (int jj = 0; jj < 8; jj++) {
            int cc = col_base + jj * 8 + tq * 2;
            float2 bv = *(const float2*)(bias + cc);
            float4 v = acc[il][jj];
            *(float2*)(o0 + cc) = make_float2(v.x + bv.x, v.y + bv.y);
            *(float2*)(o1 + cc) = make_float2(v.z + bv.x, v.w + bv.y);
        }
    }
}

// ---------------- GEMM entry: full tiles then split halves ----------------
__global__ __launch_bounds__(256, 1)
void awq_gemm_kernel(const float* __restrict__ bias, float* __restrict__ out) {
    extern __shared__ char sm[];
    const uint32_t sbase = smem_u32(sm);
    int bid = blockIdx.x;
    if (bid < FULL_TILES) {
        run_tile<4>(bid & 15, bid >> 4, 0, sm, sbase, bias, out);
    } else {
        int u = bid - FULL_TILES;
        int tle = FULL_TILES + (u >> 1);
        run_tile<2>(tle & 15, tle >> 4, u & 1, sm, sbase, bias, out);
    }
}

// ---------------- launch ----------------
extern "C" void kernel_launch(void* const* d_in, const int* in_sizes, int n_in,
                              void* d_out, int out_size) {
    const float* x     = (const float*)d_in[0];
    const int*   qw    = (const int*)d_in[1];
    const float* sc    = (const float*)d_in[2];
    const float* alpha = (const float*)d_in[3];
    const float* bias  = (const float*)d_in[4];
    float* out = (float*)d_out;

    cudaFuncSetAttribute(awq_gemm_kernel,
                         cudaFuncAttributeMaxDynamicSharedMemorySize, SMEM_BYTES);

    prep_all_kernel<<<WBLOCKS + XBLOCKS, 256>>>(x, alpha, qw, sc);

    awq_gemm_kernel<<<GRID_CTAS, 256, SMEM_BYTES>>>(bias, out);
}

// round 16
// speedup vs baseline: 1.1508x; 1.1508x over previous
#include <cuda_runtime.h>
#include <cuda_fp16.h>
#include <cstdint>

// ============================================================
// AWQLinear via fp16 mma.sync m16n8k16 (same mantissa as tf32).
// y = (x/alpha) @ W_hat^T + bias, M=4096 N=11008 K=4096.
// R14 = R11 verbatim (best measured: 256x128 tiles, 4-stage
// WAIT1 ring, cross-iter s0 prefetch, tail-wave split) with
// __ldg on prep's read-only traffic.
// ============================================================

#define IN_F   4096
#define OUT_F  11008
#define MROWS  4096
#define NKT    64
#define A_BLK_B32 8192
#define B_BLK_B32 4096
#define STAGE_BYTES ((A_BLK_B32 + B_BLK_B32) * 4)     // 48KB
#define SMEM_BYTES (4 * STAGE_BYTES)                  // 192KB
#define A_KT_BYTES (A_BLK_B32 * 4)
#define B_KT_BYTES (B_BLK_B32 * 4)

#define NTILES     1376          // 16 x 86
#define FULL_TILES 1332          // 9 waves x 148
#define SPLIT_TILES (NTILES - FULL_TILES)             // 44
#define GRID_CTAS  (FULL_TILES + 2 * SPLIT_TILES)     // 1420

#define XCHUNKS (MROWS * IN_F / 8)
#define WCHUNKS (OUT_F * IN_F / 8)
#define WBLOCKS (WCHUNKS / 256)                 // 22016
#define XBLOCKS (XCHUNKS / 256)                 // 8192

__device__ __half2 g_A[(size_t)XCHUNKS * 4];    // 32MB
__device__ __half2 g_B[(size_t)WCHUNKS * 4];    // 90MB

// ---------------- helpers ----------------
__device__ __forceinline__ uint32_t smem_u32(const void* p) {
    uint32_t a;
    asm("{ .reg .u64 t; cvta.to.shared.u64 t, %1; cvt.u32.u64 %0, t; }"
        : "=r"(a) : "l"(p));
    return a;
}
__device__ __forceinline__ void cp16(uint32_t dst, const void* src) {
    asm volatile("cp.async.cg.shared.global [%0], [%1], 16;"
                 :: "r"(dst), "l"(src) : "memory");
}
#define CP_COMMIT() asm volatile("cp.async.commit_group;" ::: "memory")
#define CP_WAIT1()  asm volatile("cp.async.wait_group 1;" ::: "memory")

__device__ __forceinline__ void mma_f16(float4& d, const uint4 a,
                                        const uint32_t b0, const uint32_t b1) {
    asm("mma.sync.aligned.m16n8k16.row.col.f32.f16.f16.f32 "
        "{%0,%1,%2,%3}, {%4,%5,%6,%7}, {%8,%9}, {%0,%1,%2,%3};"
        : "+f"(d.x), "+f"(d.y), "+f"(d.z), "+f"(d.w)
        : "r"(a.x), "r"(a.y), "r"(a.z), "r"(a.w), "r"(b0), "r"(b1));
}
__device__ __forceinline__ uint32_t h2u(__half2 h) { return *(uint32_t*)&h; }

// ---------------- merged prep: 1 thread = one 16B fragment chunk --------
__global__ void prep_all_kernel(const float* __restrict__ x,
                                const float* __restrict__ alpha,
                                const int* __restrict__ q,
                                const float* __restrict__ sc) {
    int bid = blockIdx.x;
    if (bid < WBLOCKS) {
        int j = bid * 256 + threadIdx.x;
        int blk = j >> 10, c = j & 1023;
        int th = c & 31, jp = (c >> 5) & 7, s = c >> 8;
        int nb = blk >> 6, kt = blk & 63;
        int o0 = (nb << 7) + (jp << 4) + (th >> 2);
        int k0 = (kt << 6) + (s << 4) + ((th & 3) << 1);
        int sblk = (kt << 1) + (s >> 1);
        const int* q0 = q + ((size_t)o0 << 12) + k0;
        const int* q8 = q0 + (8 << 12);
        float s0 = __ldg(sc + (o0 << 7) + sblk);
        float s1 = __ldg(sc + ((o0 + 8) << 7) + sblk);
        int2 a0 = __ldg((const int2*)(q0));
        int2 a2 = __ldg((const int2*)(q0 + 8));
        int2 b0 = __ldg((const int2*)(q8));
        int2 b2 = __ldg((const int2*)(q8 + 8));
        uint4 o;
        o.x = h2u(__floats2half2_rn((float)(a0.x - 8) * s0, (float)(a0.y - 8) * s0));
        o.y = h2u(__floats2half2_rn((float)(a2.x - 8) * s0, (float)(a2.y - 8) * s0));
        o.z = h2u(__floats2half2_rn((float)(b0.x - 8) * s1, (float)(b0.y - 8) * s1));
        o.w = h2u(__floats2half2_rn((float)(b2.x - 8) * s1, (float)(b2.y - 8) * s1));
        *(uint4*)(g_B + (size_t)j * 4) = o;
    } else {
        int j = (bid - WBLOCKS) * 256 + threadIdx.x;
        int blk = j >> 11, c = j & 2047;
        int th = c & 31, it = (c >> 5) & 15, s = c >> 9;
        int mb = blk >> 6, kt = blk & 63;
        int row0 = (mb << 8) + (it << 4) + (th >> 2);
        int k0 = (kt << 6) + (s << 4) + ((th & 3) << 1);
        const float* x0 = x + ((size_t)row0 << 12) + k0;
        const float* x8 = x0 + (8 << 12);
        float ia0 = 1.0f / __ldg(alpha + k0);
        float ia1 = 1.0f / __ldg(alpha + k0 + 1);
        float ia8 = 1.0f / __ldg(alpha + k0 + 8);
        float ia9 = 1.0f / __ldg(alpha + k0 + 9);
        float2 v00 = __ldg((const float2*)(x0));
        float2 v10 = __ldg((const float2*)(x8));
        float2 v08 = __ldg((const float2*)(x0 + 8));
        float2 v18 = __ldg((const float2*)(x8 + 8));
        uint4 o;
        o.x = h2u(__floats2half2_rn(v00.x * ia0, v00.y * ia1));
        o.y = h2u(__floats2half2_rn(v10.x * ia0, v10.y * ia1));
        o.z = h2u(__floats2half2_rn(v08.x * ia8, v08.y * ia9));
        o.w = h2u(__floats2half2_rn(v18.x * ia8, v18.y * ia9));
        *(uint4*)(g_A + (size_t)j * 4) = o;
    }
}

// ---------------- tile worker, NIL = A-itiles per warp (4 full / 2 half) ----
template<int NIL>
__device__ __forceinline__ void run_tile(int mt, int nt, int h, char* sm,
                                         uint32_t sbase,
                                         const float* __restrict__ bias,
                                         float* __restrict__ out) {
    int tid = threadIdx.x, wid = tid >> 5, t = tid & 31;
    int wm = wid & 3, wn = wid >> 2;
    const int itbase = (NIL == 4) ? (wm << 2) : (h * 8 + wm * 2);

    const char* gA = (const char*)g_A + (size_t)mt * (NKT * A_KT_BYTES);
    const char* gB = (const char*)g_B + (size_t)nt * (NKT * B_KT_BYTES);

    auto copy_stage = [&](int kt, uint32_t pbase) {
        const char* srcA = gA + (size_t)kt * A_KT_BYTES;
        if (NIL == 4) {
#pragma unroll
            for (int r = 0; r < 8; r++) {
                uint32_t off = (uint32_t)(tid * 16 + r * 4096);
                cp16(sbase + pbase + off, srcA + off);
            }
        } else {
#pragma unroll
            for (int r = 0; r < 4; r++) {         // half: itiles h*8..h*8+7
                int idx = r * 256 + tid;
                int s = idx >> 8, itl = h * 8 + ((idx >> 5) & 7), th = idx & 31;
                uint32_t off = (uint32_t)((((s << 4) + itl) << 9) + (th << 4));
                cp16(sbase + pbase + off, srcA + off);
            }
        }
        const char* srcB = gB + (size_t)kt * B_KT_BYTES;
#pragma unroll
        for (int r = 0; r < 4; r++) {
            uint32_t off = (uint32_t)(tid * 16 + r * 4096);
            cp16(sbase + pbase + A_KT_BYTES + off, srcB + off);
        }
    };

    copy_stage(0, 0); CP_COMMIT();
    copy_stage(1, STAGE_BYTES); CP_COMMIT();
    copy_stage(2, 2 * STAGE_BYTES); CP_COMMIT();

    float4 acc[NIL][8];
#pragma unroll
    for (int i = 0; i < NIL; i++)
#pragma unroll
        for (int jj = 0; jj < 8; jj++) acc[i][jj] = make_float4(0.f, 0.f, 0.f, 0.f);

    const int aoff = itbase * 512 + t * 16;
    const int boff = A_KT_BYTES + wn * 2048 + t * 16;

    uint4 fa[2][NIL], fb[2][4];
    auto load_frag = [&](int bi, const char* stage, int s) {
        const char* ab = stage + s * 8192 + aoff;
        const char* bb = stage + s * 4096 + boff;
#pragma unroll
        for (int il = 0; il < NIL; il++) fa[bi][il] = *(const uint4*)(ab + il * 512);
#pragma unroll
        for (int pl = 0; pl < 4; pl++) fb[bi][pl] = *(const uint4*)(bb + pl * 512);
    };
    auto do_mma = [&](int bi) {
#pragma unroll
        for (int il = 0; il < NIL; il++)
#pragma unroll
            for (int jj = 0; jj < 8; jj++) {
                const uint4& bp = fb[bi][jj >> 1];
                if (jj & 1) mma_f16(acc[il][jj], fa[bi][il], bp.z, bp.w);
                else        mma_f16(acc[il][jj], fa[bi][il], bp.x, bp.y);
            }
    };

    CP_WAIT1();
    __syncthreads();
    load_frag(0, sm, 0);

    auto iter = [&](int kt, int p) {
        const char* stage = sm + (size_t)p * STAGE_BYTES;
        if (kt + 3 < NKT) copy_stage(kt + 3, (uint32_t)((p + 3) & 3) * STAGE_BYTES);
        CP_COMMIT();
#pragma unroll
        for (int s = 0; s < 4; s++) {
            int cur = s & 1;
            if (s < 3) load_frag(cur ^ 1, stage, s + 1);
            else if (kt + 1 < NKT)
                load_frag(cur ^ 1, sm + (size_t)((p + 1) & 3) * STAGE_BYTES, 0);
            do_mma(cur);
        }
        CP_WAIT1();
        __syncthreads();
    };

    for (int kt = 0; kt < NKT; kt += 4) {
        iter(kt + 0, 0);
        iter(kt + 1, 1);
        iter(kt + 2, 2);
        iter(kt + 3, 3);
    }

    int quad = t >> 2, tq = t & 3;
    int col_base = nt * 128 + wn * 64;
#pragma unroll
    for (int il = 0; il < NIL; il++) {
        int r0 = mt * 256 + (itbase + il) * 16 + quad;
        float* o0 = out + (size_t)r0 * OUT_F;
        float* o1 = o0 + (size_t)8 * OUT_F;
#pragma unroll
        for (int jj = 0; jj < 8; jj++) {
            int cc = col_base + jj * 8 + tq * 2;
            float2 bv = *(const float2*)(bias + cc);
            float4 v = acc[il][jj];
            *(float2*)(o0 + cc) = make_float2(v.x + bv.x, v.y + bv.y);
            *(float2*)(o1 + cc) = make_float2(v.z + bv.x, v.w + bv.y);
        }
    }
}

// ---------------- GEMM entry: full tiles then split halves ----------------
__global__ __launch_bounds__(256, 1)
void awq_gemm_kernel(const float* __restrict__ bias, float* __restrict__ out) {
    extern __shared__ char sm[];
    const uint32_t sbase = smem_u32(sm);
    int bid = blockIdx.x;
    if (bid < FULL_TILES) {
        run_tile<4>(bid & 15, bid >> 4, 0, sm, sbase, bias, out);
    } else {
        int u = bid - FULL_TILES;
        int tle = FULL_TILES + (u >> 1);
        run_tile<2>(tle & 15, tle >> 4, u & 1, sm, sbase, bias, out);
    }
}

// ---------------- launch ----------------
extern "C" void kernel_launch(void* const* d_in, const int* in_sizes, int n_in,
                              void* d_out, int out_size) {
    const float* x     = (const float*)d_in[0];
    const int*   qw    = (const int*)d_in[1];
    const float* sc    = (const float*)d_in[2];
    const float* alpha = (const float*)d_in[3];
    const float* bias  = (const float*)d_in[4];
    float* out = (float*)d_out;

    cudaFuncSetAttribute(awq_gemm_kernel,
                         cudaFuncAttributeMaxDynamicSharedMemorySize, SMEM_BYTES);

    prep_all_kernel<<<WBLOCKS + XBLOCKS, 256>>>(x, alpha, qw, sc);

    awq_gemm_kernel<<<GRID_CTAS, 256, SMEM_BYTES>>>(bias, out);
}

// round 17
// speedup vs baseline: 1.1566x; 1.0050x over previous
#include <cuda_runtime.h>
#include <cuda_fp16.h>
#include <cstdint>

// ============================================================
// AWQLinear via fp16 mma.sync m16n8k16 (same mantissa as tf32).
// y = (x/alpha) @ W_hat^T + bias, M=4096 N=11008 K=4096.
// R16 = R11 pipeline with the CTA rendezvous (bar.sync) replaced
// by a split mbarrier: arrive at iter end, wait mid-next-iter,
// with s0+s1 mma hoisted before the wait to absorb warp skew.
// ============================================================

#define IN_F   4096
#define OUT_F  11008
#define MROWS  4096
#define NKT    64
#define A_BLK_B32 8192
#define B_BLK_B32 4096
#define STAGE_BYTES ((A_BLK_B32 + B_BLK_B32) * 4)     // 48KB
#define SMEM_BYTES (4 * STAGE_BYTES + 16)             // 192KB + mbar
#define A_KT_BYTES (A_BLK_B32 * 4)
#define B_KT_BYTES (B_BLK_B32 * 4)

#define NTILES     1376          // 16 x 86
#define FULL_TILES 1332          // 9 waves x 148
#define SPLIT_TILES (NTILES - FULL_TILES)             // 44
#define GRID_CTAS  (FULL_TILES + 2 * SPLIT_TILES)     // 1420

#define XCHUNKS (MROWS * IN_F / 8)
#define WCHUNKS (OUT_F * IN_F / 8)
#define WBLOCKS (WCHUNKS / 256)                 // 22016
#define XBLOCKS (XCHUNKS / 256)                 // 8192

__device__ __half2 g_A[(size_t)XCHUNKS * 4];    // 32MB
__device__ __half2 g_B[(size_t)WCHUNKS * 4];    // 90MB

// ---------------- helpers ----------------
__device__ __forceinline__ uint32_t smem_u32(const void* p) {
    uint32_t a;
    asm("{ .reg .u64 t; cvta.to.shared.u64 t, %1; cvt.u32.u64 %0, t; }"
        : "=r"(a) : "l"(p));
    return a;
}
__device__ __forceinline__ void cp16(uint32_t dst, const void* src) {
    asm volatile("cp.async.cg.shared.global [%0], [%1], 16;"
                 :: "r"(dst), "l"(src) : "memory");
}
#define CP_COMMIT() asm volatile("cp.async.commit_group;" ::: "memory")
#define CP_WAIT1()  asm volatile("cp.async.wait_group 1;" ::: "memory")

#define MBAR_INIT(addr, cnt) \
    asm volatile("mbarrier.init.shared.b64 [%0], %1;" \
                 :: "r"(addr), "r"((uint32_t)(cnt)) : "memory")
#define MBAR_ARRIVE(addr) \
    asm volatile("mbarrier.arrive.release.cta.shared::cta.b64 _, [%0];" \
                 :: "r"(addr) : "memory")
__device__ __forceinline__ void mbar_wait(uint32_t mbar, uint32_t parity) {
    uint32_t done;
    asm volatile(
        "{\n\t.reg .pred p;\n\t"
        "mbarrier.try_wait.parity.acquire.cta.shared::cta.b64 p, [%1], %2;\n\t"
        "selp.b32 %0, 1, 0, p;\n\t}"
        : "=r"(done) : "r"(mbar), "r"(parity) : "memory");
    if (!done) {
        asm volatile(
            "{\n\t.reg .pred P1;\n\t"
            "WL_%=:\n\t"
            "mbarrier.try_wait.parity.acquire.cta.shared::cta.b64 P1, [%0], %1, 0x989680;\n\t"
            "@P1 bra.uni WD_%=;\n\t"
            "bra.uni WL_%=;\n\t"
            "WD_%=:\n\t}"
            :: "r"(mbar), "r"(parity) : "memory");
    }
}

__device__ __forceinline__ void mma_f16(float4& d, const uint4 a,
                                        const uint32_t b0, const uint32_t b1) {
    asm("mma.sync.aligned.m16n8k16.row.col.f32.f16.f16.f32 "
        "{%0,%1,%2,%3}, {%4,%5,%6,%7}, {%8,%9}, {%0,%1,%2,%3};"
        : "+f"(d.x), "+f"(d.y), "+f"(d.z), "+f"(d.w)
        : "r"(a.x), "r"(a.y), "r"(a.z), "r"(a.w), "r"(b0), "r"(b1));
}
__device__ __forceinline__ uint32_t h2u(__half2 h) { return *(uint32_t*)&h; }

// ---------------- merged prep: 1 thread = one 16B fragment chunk --------
__global__ void prep_all_kernel(const float* __restrict__ x,
                                const float* __restrict__ alpha,
                                const int* __restrict__ q,
                                const float* __restrict__ sc) {
    int bid = blockIdx.x;
    if (bid < WBLOCKS) {
        int j = bid * 256 + threadIdx.x;
        int blk = j >> 10, c = j & 1023;
        int th = c & 31, jp = (c >> 5) & 7, s = c >> 8;
        int nb = blk >> 6, kt = blk & 63;
        int o0 = (nb << 7) + (jp << 4) + (th >> 2);
        int k0 = (kt << 6) + (s << 4) + ((th & 3) << 1);
        int sblk = (kt << 1) + (s >> 1);
        const int* q0 = q + ((size_t)o0 << 12) + k0;
        const int* q8 = q0 + (8 << 12);
        float s0 = __ldg(sc + (o0 << 7) + sblk);
        float s1 = __ldg(sc + ((o0 + 8) << 7) + sblk);
        int2 a0 = __ldg((const int2*)(q0));
        int2 a2 = __ldg((const int2*)(q0 + 8));
        int2 b0 = __ldg((const int2*)(q8));
        int2 b2 = __ldg((const int2*)(q8 + 8));
        uint4 o;
        o.x = h2u(__floats2half2_rn((float)(a0.x - 8) * s0, (float)(a0.y - 8) * s0));
        o.y = h2u(__floats2half2_rn((float)(a2.x - 8) * s0, (float)(a2.y - 8) * s0));
        o.z = h2u(__floats2half2_rn((float)(b0.x - 8) * s1, (float)(b0.y - 8) * s1));
        o.w = h2u(__floats2half2_rn((float)(b2.x - 8) * s1, (float)(b2.y - 8) * s1));
        *(uint4*)(g_B + (size_t)j * 4) = o;
    } else {
        int j = (bid - WBLOCKS) * 256 + threadIdx.x;
        int blk = j >> 11, c = j & 2047;
        int th = c & 31, it = (c >> 5) & 15, s = c >> 9;
        int mb = blk >> 6, kt = blk & 63;
        int row0 = (mb << 8) + (it << 4) + (th >> 2);
        int k0 = (kt << 6) + (s << 4) + ((th & 3) << 1);
        const float* x0 = x + ((size_t)row0 << 12) + k0;
        const float* x8 = x0 + (8 << 12);
        float ia0 = 1.0f / __ldg(alpha + k0);
        float ia1 = 1.0f / __ldg(alpha + k0 + 1);
        float ia8 = 1.0f / __ldg(alpha + k0 + 8);
        float ia9 = 1.0f / __ldg(alpha + k0 + 9);
        float2 v00 = __ldg((const float2*)(x0));
        float2 v10 = __ldg((const float2*)(x8));
        float2 v08 = __ldg((const float2*)(x0 + 8));
        float2 v18 = __ldg((const float2*)(x8 + 8));
        uint4 o;
        o.x = h2u(__floats2half2_rn(v00.x * ia0, v00.y * ia1));
        o.y = h2u(__floats2half2_rn(v10.x * ia0, v10.y * ia1));
        o.z = h2u(__floats2half2_rn(v08.x * ia8, v08.y * ia9));
        o.w = h2u(__floats2half2_rn(v18.x * ia8, v18.y * ia9));
        *(uint4*)(g_A + (size_t)j * 4) = o;
    }
}

// ---------------- tile worker, NIL = A-itiles per warp (4 full / 2 half) ----
template<int NIL>
__device__ __forceinline__ void run_tile(int mt, int nt, int h, char* sm,
                                         uint32_t sbase,
                                         const float* __restrict__ bias,
                                         float* __restrict__ out) {
    int tid = threadIdx.x, wid = tid >> 5, t = tid & 31;
    int wm = wid & 3, wn = wid >> 2;
    const int itbase = (NIL == 4) ? (wm << 2) : (h * 8 + wm * 2);
    const uint32_t mbar = sbase + 4 * STAGE_BYTES;

    const char* gA = (const char*)g_A + (size_t)mt * (NKT * A_KT_BYTES);
    const char* gB = (const char*)g_B + (size_t)nt * (NKT * B_KT_BYTES);

    auto copy_stage = [&](int kt, uint32_t pbase) {
        const char* srcA = gA + (size_t)kt * A_KT_BYTES;
        if (NIL == 4) {
#pragma unroll
            for (int r = 0; r < 8; r++) {
                uint32_t off = (uint32_t)(tid * 16 + r * 4096);
                cp16(sbase + pbase + off, srcA + off);
            }
        } else {
#pragma unroll
            for (int r = 0; r < 4; r++) {         // half: itiles h*8..h*8+7
                int idx = r * 256 + tid;
                int s = idx >> 8, itl = h * 8 + ((idx >> 5) & 7), th = idx & 31;
                uint32_t off = (uint32_t)((((s << 4) + itl) << 9) + (th << 4));
                cp16(sbase + pbase + off, srcA + off);
            }
        }
        const char* srcB = gB + (size_t)kt * B_KT_BYTES;
#pragma unroll
        for (int r = 0; r < 4; r++) {
            uint32_t off = (uint32_t)(tid * 16 + r * 4096);
            cp16(sbase + pbase + A_KT_BYTES + off, srcB + off);
        }
    };

    if (tid == 0) MBAR_INIT(mbar, 256);

    copy_stage(0, 0); CP_COMMIT();
    copy_stage(1, STAGE_BYTES); CP_COMMIT();
    copy_stage(2, 2 * STAGE_BYTES); CP_COMMIT();

    float4 acc[NIL][8];
#pragma unroll
    for (int i = 0; i < NIL; i++)
#pragma unroll
        for (int jj = 0; jj < 8; jj++) acc[i][jj] = make_float4(0.f, 0.f, 0.f, 0.f);

    const int aoff = itbase * 512 + t * 16;
    const int boff = A_KT_BYTES + wn * 2048 + t * 16;

    uint4 fa[2][NIL], fb[2][4];
    auto load_frag = [&](int bi, const char* stage, int s) {
        const char* ab = stage + s * 8192 + aoff;
        const char* bb = stage + s * 4096 + boff;
#pragma unroll
        for (int il = 0; il < NIL; il++) fa[bi][il] = *(const uint4*)(ab + il * 512);
#pragma unroll
        for (int pl = 0; pl < 4; pl++) fb[bi][pl] = *(const uint4*)(bb + pl * 512);
    };
    auto do_mma = [&](int bi) {
#pragma unroll
        for (int il = 0; il < NIL; il++)
#pragma unroll
            for (int jj = 0; jj < 8; jj++) {
                const uint4& bp = fb[bi][jj >> 1];
                if (jj & 1) mma_f16(acc[il][jj], fa[bi][il], bp.z, bp.w);
                else        mma_f16(acc[il][jj], fa[bi][il], bp.x, bp.y);
            }
    };

    // prologue: stages 0,1 arrived; publish init + copies; completion #0
    CP_WAIT1();
    __syncthreads();
    MBAR_ARRIVE(mbar);               // phase 0 completes (no one stalls on it)
    load_frag(0, sm, 0);

    // iter kt: [s0 mma, s1 mma] [mb_wait #kt] [copy kt+3] [s2, s3+prefetch]
    //          [cp.wait1] [mb_arrive -> completion #kt+1]
    auto iter = [&](int kt, int p) {
        const char* stage = sm + (size_t)p * STAGE_BYTES;
        load_frag(1, stage, 1);  do_mma(0);
        load_frag(0, stage, 2);  do_mma(1);
        mbar_wait(mbar, (uint32_t)(kt & 1));      // completion #kt
        if (kt + 3 < NKT) copy_stage(kt + 3, (uint32_t)((p + 3) & 3) * STAGE_BYTES);
        CP_COMMIT();
        load_frag(1, stage, 3);  do_mma(0);
        if (kt + 1 < NKT)
            load_frag(0, sm + (size_t)((p + 1) & 3) * STAGE_BYTES, 0);
        do_mma(1);
        CP_WAIT1();
        MBAR_ARRIVE(mbar);
    };

    for (int kt = 0; kt < NKT; kt += 4) {
        iter(kt + 0, 0);
        iter(kt + 1, 1);
        iter(kt + 2, 2);
        iter(kt + 3, 3);
    }

    int quad = t >> 2, tq = t & 3;
    int col_base = nt * 128 + wn * 64;
#pragma unroll
    for (int il = 0; il < NIL; il++) {
        int r0 = mt * 256 + (itbase + il) * 16 + quad;
        float* o0 = out + (size_t)r0 * OUT_F;
        float* o1 = o0 + (size_t)8 * OUT_F;
#pragma unroll
        for (int jj = 0; jj < 8; jj++) {
            int cc = col_base + jj * 8 + tq * 2;
            float2 bv = *(const float2*)(bias + cc);
            float4 v = acc[il][jj];
            *(float2*)(o0 + cc) = make_float2(v.x + bv.x, v.y + bv.y);
            *(float2*)(o1 + cc) = make_float2(v.z + bv.x, v.w + bv.y);
        }
    }
}

// ---------------- GEMM entry: full tiles then split halves ----------------
__global__ __launch_bounds__(256, 1)
void awq_gemm_kernel(const float* __restrict__ bias, float* __restrict__ out) {
    extern __shared__ char sm[];
    const uint32_t sbase = smem_u32(sm);
    int bid = blockIdx.x;
    if (bid < FULL_TILES) {
        run_tile<4>(bid & 15, bid >> 4, 0, sm, sbase, bias, out);
    } else {
        int u = bid - FULL_TILES;
        int tle = FULL_TILES + (u >> 1);
        run_tile<2>(tle & 15, tle >> 4, u & 1, sm, sbase, bias, out);
    }
}

// ---------------- launch ----------------
extern "C" void kernel_launch(void* const* d_in, const int* in_sizes, int n_in,
                              void* d_out, int out_size) {
    const float* x     = (const float*)d_in[0];
    const int*   qw    = (const int*)d_in[1];
    const float* sc    = (const float*)d_in[2];
    const float* alpha = (const float*)d_in[3];
    const float* bias  = (const float*)d_in[4];
    float* out = (float*)d_out;

    cudaFuncSetAttribute(awq_gemm_kernel,
                         cudaFuncAttributeMaxDynamicSharedMemorySize, SMEM_BYTES);

    prep_all_kernel<<<WBLOCKS + XBLOCKS, 256>>>(x, alpha, qw, sc);

    awq_gemm_kernel<<<GRID_CTAS, 256, SMEM_BYTES>>>(bias, out);
}